// round 5
// baseline (speedup 1.0000x reference)
#include <cuda_runtime.h>
#include <cstdint>
#include <cstdio>

// Problem constants
#define PB 2
#define PS 2048
#define PD 2048
#define PH 32
#define PKV 8
#define PHD 64
#define PM (PB * PS)          // 4096 rows of x
#define PG (PH / PKV)         // 4

// ---------------------------------------------------------------------------
// Scratch (device globals; no runtime allocation allowed)
// ---------------------------------------------------------------------------
__device__ float g_Q[(size_t)PM * PD];             // (4096, 2048)  32MB
__device__ float g_K[(size_t)PM * (PKV * PHD)];    // (4096, 512)    8MB
__device__ float g_V[(size_t)PM * (PKV * PHD)];    // (4096, 512)    8MB
__device__ float g_AO[(size_t)PM * PD];            // (4096, 2048)  32MB

// ---------------------------------------------------------------------------
// TF32 / async helpers
// ---------------------------------------------------------------------------
__device__ __forceinline__ uint32_t f2tf32(float x) {
    uint32_t r;
    asm("cvt.rna.tf32.f32 %0, %1;" : "=r"(r) : "f"(x));
    return r;
}

__device__ __forceinline__ void mma_tf32(float* d, const uint32_t* a, const uint32_t* b) {
    asm volatile(
        "mma.sync.aligned.m16n8k8.row.col.f32.tf32.tf32.f32 "
        "{%0,%1,%2,%3}, {%4,%5,%6,%7}, {%8,%9}, {%0,%1,%2,%3};"
        : "+f"(d[0]), "+f"(d[1]), "+f"(d[2]), "+f"(d[3])
        : "r"(a[0]), "r"(a[1]), "r"(a[2]), "r"(a[3]),
          "r"(b[0]), "r"(b[1]));
}

__device__ __forceinline__ uint32_t smem_u32(const void* p) {
    uint32_t a;
    asm("{ .reg .u64 t; cvta.to.shared.u64 t, %1; cvt.u32.u64 %0, t; }"
        : "=r"(a) : "l"(p));
    return a;
}

__device__ __forceinline__ void cpa16(uint32_t dst, const void* src) {
    asm volatile("cp.async.cg.shared.global [%0], [%1], 16;" :: "r"(dst), "l"(src));
}
#define CP_COMMIT() asm volatile("cp.async.commit_group;")
#define CP_WAIT1()  asm volatile("cp.async.wait_group 1;")

// ---------------------------------------------------------------------------
// TF32 tensor-core GEMM (NT): C[M,N] = A[M,K] @ B[N,K]^T (row-major, K contig)
// 128x128 block tile, BK=32, 3-stage cp.async pipeline, 256 threads = 8 warps
// (2x4), warp tile 64x32. Smem holds fp32; tf32 cvt at fragment load.
// ---------------------------------------------------------------------------
#define GSTG 3
#define GBK  32
#define GST  36   // row stride (floats): 16B-aligned rows; conflict-free frags
#define GEMM_SMEM (2 * GSTG * 128 * GST * 4)

__device__ __forceinline__ void gemm_body(float* sm, const float* __restrict__ A,
                                          const float* __restrict__ B,
                                          float* __restrict__ C, int N, int K)
{
    float* As = sm;                         // [GSTG][128*GST]
    float* Bs = sm + GSTG * 128 * GST;

    const int tid  = threadIdx.x;
    const int lane = tid & 31;
    const int warp = tid >> 5;
    const int g    = lane >> 2;
    const int tig  = lane & 3;
    const int warp_m = warp >> 2;        // 0..1 -> m offset *64
    const int warp_n = warp & 3;         // 0..3 -> n offset *32
    const int bm = blockIdx.y;
    const int bn = blockIdx.x;

    const float* Ab = A + (size_t)bm * 128 * K;
    const float* Bb = B + (size_t)bn * 128 * K;

    // per-thread copy coordinates: 4 float4 per array per stage
    int lrow[4], lks[4];
#pragma unroll
    for (int r = 0; r < 4; r++) {
        int e = tid + 256 * r;           // 0..1023
        lrow[r] = e >> 3;                // 0..127
        lks[r]  = (e & 7) << 2;          // 0,4,...,28
    }
    const uint32_t asb = smem_u32(As);
    const uint32_t bsb = smem_u32(Bs);

    float acc[4][4][4];
#pragma unroll
    for (int i = 0; i < 4; i++)
#pragma unroll
        for (int j = 0; j < 4; j++)
#pragma unroll
            for (int r = 0; r < 4; r++) acc[i][j][r] = 0.f;

    const int T = K / GBK;

    // prologue: fill stages 0..GSTG-2
#pragma unroll
    for (int s = 0; s < GSTG - 1; s++) {
        int k0 = s * GBK;
#pragma unroll
        for (int r = 0; r < 4; r++) {
            uint32_t off = (uint32_t)(s * 128 * GST + lrow[r] * GST + lks[r]) * 4u;
            cpa16(asb + off, Ab + (size_t)lrow[r] * K + k0 + lks[r]);
            cpa16(bsb + off, Bb + (size_t)lrow[r] * K + k0 + lks[r]);
        }
        CP_COMMIT();
    }

    for (int t = 0; t < T; t++) {
        CP_WAIT1();
        __syncthreads();

        // issue stage t+GSTG-1
        if (t + GSTG - 1 < T) {
            int s  = (t + GSTG - 1) % GSTG;
            int k0 = (t + GSTG - 1) * GBK;
#pragma unroll
            for (int r = 0; r < 4; r++) {
                uint32_t off = (uint32_t)(s * 128 * GST + lrow[r] * GST + lks[r]) * 4u;
                cpa16(asb + off, Ab + (size_t)lrow[r] * K + k0 + lks[r]);
                cpa16(bsb + off, Bb + (size_t)lrow[r] * K + k0 + lks[r]);
            }
        }
        CP_COMMIT();

        const float* Af = As + (t % GSTG) * 128 * GST;
        const float* Bf = Bs + (t % GSTG) * 128 * GST;

#pragma unroll
        for (int ks = 0; ks < GBK; ks += 8) {
            uint32_t afr[4][4], bfr[4][2];
#pragma unroll
            for (int i = 0; i < 4; i++) {
                int row = warp_m * 64 + i * 16;
                afr[i][0] = f2tf32(Af[(row + g)     * GST + ks + tig]);
                afr[i][1] = f2tf32(Af[(row + g + 8) * GST + ks + tig]);
                afr[i][2] = f2tf32(Af[(row + g)     * GST + ks + tig + 4]);
                afr[i][3] = f2tf32(Af[(row + g + 8) * GST + ks + tig + 4]);
            }
#pragma unroll
            for (int j = 0; j < 4; j++) {
                int col = warp_n * 32 + j * 8;
                bfr[j][0] = f2tf32(Bf[(col + g) * GST + ks + tig]);
                bfr[j][1] = f2tf32(Bf[(col + g) * GST + ks + tig + 4]);
            }
#pragma unroll
            for (int i = 0; i < 4; i++)
#pragma unroll
                for (int j = 0; j < 4; j++)
                    mma_tf32(acc[i][j], afr[i], bfr[j]);
        }
    }

    // epilogue
#pragma unroll
    for (int i = 0; i < 4; i++) {
        int row0 = bm * 128 + warp_m * 64 + i * 16 + g;
#pragma unroll
        for (int j = 0; j < 4; j++) {
            int col = bn * 128 + warp_n * 32 + j * 8 + 2 * tig;
            *(float2*)(C + (size_t)row0 * N + col)       = make_float2(acc[i][j][0], acc[i][j][1]);
            *(float2*)(C + (size_t)(row0 + 8) * N + col) = make_float2(acc[i][j][2], acc[i][j][3]);
        }
    }
}

__global__ __launch_bounds__(256, 2)
void gemm_one(const float* __restrict__ A, const float* __restrict__ B,
              float* __restrict__ C, int N, int K)
{
    extern __shared__ float sm[];
    gemm_body(sm, A, B, C, N, K);
}

// K and V projections merged: blockIdx.z selects weight/output pair.
__global__ __launch_bounds__(256, 2)
void gemm_kv(const float* __restrict__ x,
             const float* __restrict__ Wk, const float* __restrict__ Wv,
             float* __restrict__ Kp, float* __restrict__ Vp)
{
    extern __shared__ float sm[];
    if (blockIdx.z == 0) gemm_body(sm, x, Wk, Kp, PKV * PHD, PD);
    else                 gemm_body(sm, x, Wv, Vp, PKV * PHD, PD);
}

// ---------------------------------------------------------------------------
// RoPE (in place).  X viewed as (PM, nheads, 64); pairs (d, d+32), d<32.
// ---------------------------------------------------------------------------
__global__ void rope_kernel(float* __restrict__ X, const float* __restrict__ cs,
                            const float* __restrict__ sn, int nheads)
{
    int i = blockIdx.x * blockDim.x + threadIdx.x;
    int total = PM * nheads * 32;
    if (i >= total) return;
    int d   = i & 31;
    int h   = (i >> 5) % nheads;
    int row = i / (32 * nheads);
    int s   = row & (PS - 1);
    float c = cs[s * 32 + d];
    float sv = sn[s * 32 + d];
    float* base = X + ((size_t)row * nheads + h) * 64;
    float x1 = base[d];
    float x2 = base[d + 32];
    base[d]      = x1 * c - x2 * sv;
    base[d + 32] = x1 * sv + x2 * c;
}

// ---------------------------------------------------------------------------
// Causal flash attention, tf32 tensor cores (unchanged from R4).
// ---------------------------------------------------------------------------
#define AQP 68
#define FA_SMEM ((4 * 64 * AQP + 3 * 64) * 4)

__global__ __launch_bounds__(256, 2)
void flash_attn_mma(const float* __restrict__ Q, const float* __restrict__ Kg,
                    const float* __restrict__ Vg, float* __restrict__ AO)
{
    extern __shared__ float smf[];
    uint32_t* Qs = (uint32_t*)smf;                 // [64][AQP] tf32  [m][d]
    uint32_t* Ks = Qs + 64 * AQP;                  // [64][AQP] tf32  [n][d]
    uint32_t* Vs = Ks + 64 * AQP;                  // [64][AQP] tf32  [k][d]
    float*    Ssf = (float*)(Vs + 64 * AQP);       // [64][AQP] scores / P
    uint32_t* Ssu = (uint32_t*)Ssf;
    float* row_m = Ssf + 64 * AQP;
    float* row_l = row_m + 64;
    float* row_a = row_l + 64;

    const int qt = blockIdx.x;
    const int h  = blockIdx.y;
    const int b  = blockIdx.z;
    const int kvh = h >> 2;
    const int tid  = threadIdx.x;
    const int lane = tid & 31;
    const int warp = tid >> 5;
    const int g    = lane >> 2;
    const int tig  = lane & 3;
    const int warp_m = warp >> 1;    // 0..3 -> 16 rows each
    const int warp_n = warp & 1;     // 0..1 -> 32 cols each

    const float* Qbase = Q + ((size_t)(b * PS + qt * 64)) * (PH * PHD) + h * PHD;

#pragma unroll
    for (int r = 0; r < 4; r++) {
        int e   = tid + 256 * r;
        int row = e >> 4;
        int ds  = (e & 15) << 2;
        float4 v = *(const float4*)(Qbase + (size_t)row * (PH * PHD) + ds);
        uint4 u = make_uint4(f2tf32(v.x), f2tf32(v.y), f2tf32(v.z), f2tf32(v.w));
        *(uint4*)&Qs[row * AQP + ds] = u;
    }
    if (tid < 64) { row_m[tid] = -1e30f; row_l[tid] = 0.f; }

    float o[4][4];
#pragma unroll
    for (int j = 0; j < 4; j++)
#pragma unroll
        for (int r = 0; r < 4; r++) o[j][r] = 0.f;

    for (int kt = 0; kt <= qt; kt++) {
        const float* Kbase = Kg + ((size_t)(b * PS + kt * 64)) * (PKV * PHD) + kvh * PHD;
        const float* Vbase = Vg + ((size_t)(b * PS + kt * 64)) * (PKV * PHD) + kvh * PHD;

        __syncthreads();

#pragma unroll
        for (int r = 0; r < 4; r++) {
            int e   = tid + 256 * r;
            int row = e >> 4;
            int ds  = (e & 15) << 2;
            float4 kv = *(const float4*)(Kbase + (size_t)row * (PKV * PHD) + ds);
            *(uint4*)&Ks[row * AQP + ds] =
                make_uint4(f2tf32(kv.x), f2tf32(kv.y), f2tf32(kv.z), f2tf32(kv.w));
            float4 vv = *(const float4*)(Vbase + (size_t)row * (PKV * PHD) + ds);
            *(uint4*)&Vs[row * AQP + ds] =
                make_uint4(f2tf32(vv.x), f2tf32(vv.y), f2tf32(vv.z), f2tf32(vv.w));
        }
        __syncthreads();

        float s_[4][4];
#pragma unroll
        for (int j = 0; j < 4; j++)
#pragma unroll
            for (int r = 0; r < 4; r++) s_[j][r] = 0.f;

        const int rowbase = warp_m * 16;
        const int colbase = warp_n * 32;
#pragma unroll
        for (int ks = 0; ks < 64; ks += 8) {
            uint32_t afr[4], bfr[4][2];
            afr[0] = Qs[(rowbase + g)     * AQP + ks + tig];
            afr[1] = Qs[(rowbase + g + 8) * AQP + ks + tig];
            afr[2] = Qs[(rowbase + g)     * AQP + ks + tig + 4];
            afr[3] = Qs[(rowbase + g + 8) * AQP + ks + tig + 4];
#pragma unroll
            for (int j = 0; j < 4; j++) {
                int col = colbase + j * 8;
                bfr[j][0] = Ks[(col + g) * AQP + ks + tig];
                bfr[j][1] = Ks[(col + g) * AQP + ks + tig + 4];
            }
#pragma unroll
            for (int j = 0; j < 4; j++)
                mma_tf32(s_[j], afr, bfr[j]);
        }

        const int qr0 = qt * 64 + rowbase + g;
#pragma unroll
        for (int j = 0; j < 4; j++) {
            int c0 = colbase + j * 8 + 2 * tig;
            int kc0 = kt * 64 + c0;
            float v0 = s_[j][0] * 0.125f, v1 = s_[j][1] * 0.125f;
            float v2 = s_[j][2] * 0.125f, v3 = s_[j][3] * 0.125f;
            if (kc0     > qr0)     v0 = -1e30f;
            if (kc0 + 1 > qr0)     v1 = -1e30f;
            if (kc0     > qr0 + 8) v2 = -1e30f;
            if (kc0 + 1 > qr0 + 8) v3 = -1e30f;
            *(float2*)&Ssf[(rowbase + g)     * AQP + c0] = make_float2(v0, v1);
            *(float2*)&Ssf[(rowbase + g + 8) * AQP + c0] = make_float2(v2, v3);
        }
        __syncthreads();

        {
            const int row = tid >> 2;
            const int p   = tid & 3;
            float* Pr = Ssf + row * AQP + p * 16;
            float mx = -1e30f;
#pragma unroll
            for (int n = 0; n < 16; n++) mx = fmaxf(mx, Pr[n]);
            mx = fmaxf(mx, __shfl_xor_sync(0xffffffffu, mx, 1));
            mx = fmaxf(mx, __shfl_xor_sync(0xffffffffu, mx, 2));
            float mold = row_m[row];
            float newm = fmaxf(mold, mx);
            float ssum = 0.f;
            uint32_t* Pu = Ssu + row * AQP + p * 16;
#pragma unroll
            for (int n = 0; n < 16; n++) {
                float e = __expf(Pr[n] - newm);
                ssum += e;
                Pu[n] = f2tf32(e);
            }
            ssum += __shfl_xor_sync(0xffffffffu, ssum, 1);
            ssum += __shfl_xor_sync(0xffffffffu, ssum, 2);
            if (p == 0) {
                float alpha = __expf(mold - newm);
                row_m[row] = newm;
                row_l[row] = row_l[row] * alpha + ssum;
                row_a[row] = alpha;
            }
        }
        __syncthreads();

        float al0 = row_a[rowbase + g];
        float al1 = row_a[rowbase + g + 8];
#pragma unroll
        for (int j = 0; j < 4; j++) {
            o[j][0] *= al0; o[j][1] *= al0;
            o[j][2] *= al1; o[j][3] *= al1;
        }
#pragma unroll
        for (int ks = 0; ks < 64; ks += 8) {
            uint32_t afr[4], bfr[4][2];
            afr[0] = Ssu[(rowbase + g)     * AQP + ks + tig];
            afr[1] = Ssu[(rowbase + g + 8) * AQP + ks + tig];
            afr[2] = Ssu[(rowbase + g)     * AQP + ks + tig + 4];
            afr[3] = Ssu[(rowbase + g + 8) * AQP + ks + tig + 4];
#pragma unroll
            for (int j = 0; j < 4; j++) {
                int col = colbase + j * 8;
                bfr[j][0] = Vs[(ks + tig)     * AQP + col + g];
                bfr[j][1] = Vs[(ks + tig + 4) * AQP + col + g];
            }
#pragma unroll
            for (int j = 0; j < 4; j++)
                mma_tf32(o[j], afr, bfr[j]);
        }
    }

    float il0 = 1.0f / row_l[warp_m * 16 + g];
    float il1 = 1.0f / row_l[warp_m * 16 + g + 8];
    float* Ob = AO + ((size_t)(b * PS + qt * 64)) * (PH * PHD) + h * PHD;
    const int r0 = warp_m * 16 + g;
#pragma unroll
    for (int j = 0; j < 4; j++) {
        int c0 = warp_n * 32 + j * 8 + 2 * tig;
        *(float2*)(Ob + (size_t)r0 * (PH * PHD) + c0) =
            make_float2(o[j][0] * il0, o[j][1] * il0);
        *(float2*)(Ob + (size_t)(r0 + 8) * (PH * PHD) + c0) =
            make_float2(o[j][2] * il1, o[j][3] * il1);
    }
}

// ---------------------------------------------------------------------------
// Launch
// ---------------------------------------------------------------------------
extern "C" void kernel_launch(void* const* d_in, const int* in_sizes, int n_in,
                              void* d_out, int out_size)
{
    (void)in_sizes; (void)n_in; (void)out_size;
    const float* x  = (const float*)d_in[0];
    const float* cs = (const float*)d_in[1];
    const float* sn = (const float*)d_in[2];
    const float* Wq = (const float*)d_in[3];
    const float* Wk = (const float*)d_in[4];
    const float* Wv = (const float*)d_in[5];
    const float* Wo = (const float*)d_in[6];
    float* out = (float*)d_out;

    float *Qp, *Kp, *Vp, *AOp;
    cudaGetSymbolAddress((void**)&Qp, g_Q);
    cudaGetSymbolAddress((void**)&Kp, g_K);
    cudaGetSymbolAddress((void**)&Vp, g_V);
    cudaGetSymbolAddress((void**)&AOp, g_AO);

    cudaFuncSetAttribute(gemm_one, cudaFuncAttributeMaxDynamicSharedMemorySize, GEMM_SMEM);
    cudaFuncSetAttribute(gemm_kv,  cudaFuncAttributeMaxDynamicSharedMemorySize, GEMM_SMEM);
    cudaFuncSetAttribute(flash_attn_mma, cudaFuncAttributeMaxDynamicSharedMemorySize, FA_SMEM);

    // Q projection (tf32, cp.async pipelined)
    gemm_one<<<dim3(PD / 128, PM / 128), 256, GEMM_SMEM>>>(x, Wq, Qp, PD, PD);
    // K + V projections merged
    gemm_kv<<<dim3((PKV * PHD) / 128, PM / 128, 2), 256, GEMM_SMEM>>>(x, Wk, Wv, Kp, Vp);

    // RoPE on Q and K
    rope_kernel<<<(PM * PH * 32) / 256, 256>>>(Qp, cs, sn, PH);
    rope_kernel<<<(PM * PKV * 32) / 256, 256>>>(Kp, cs, sn, PKV);

    // causal flash attention (tf32 tensor cores)
    flash_attn_mma<<<dim3(PS / 64, PH, PB), 256, FA_SMEM>>>(Qp, Kp, Vp, AOp);

    // output projection
    gemm_one<<<dim3(PD / 128, PM / 128), 256, GEMM_SMEM>>>(AOp, Wo, out, PD, PD);
}

// round 11
// speedup vs baseline: 1.8673x; 1.8673x over previous
#include <cuda_runtime.h>
#include <cuda_fp16.h>
#include <cstdint>
#include <cstdio>

// Problem constants
#define PB 2
#define PS 2048
#define PD 2048
#define PH 32
#define PKV 8
#define PHD 64
#define PM (PB * PS)          // 4096 rows of x
#define PG (PH / PKV)         // 4

// ---------------------------------------------------------------------------
// Scratch (device globals; no runtime allocation allowed)
// ---------------------------------------------------------------------------
__device__ float g_Q[(size_t)PM * PD];             // (4096, 2048)  32MB
__device__ float g_K[(size_t)PM * (PKV * PHD)];    // (4096, 512)    8MB
__device__ float g_V[(size_t)PM * (PKV * PHD)];    // (4096, 512)    8MB
__device__ float g_AO[(size_t)PM * PD];            // (4096, 2048)  32MB

// ---------------------------------------------------------------------------
// fp16 helpers
// ---------------------------------------------------------------------------
__device__ __forceinline__ uint32_t packh2(float lo, float hi) {
    __half2 h = __floats2half2_rn(lo, hi);   // lo -> low 16 bits
    return *(uint32_t*)&h;
}

// mma.m16n8k16 fp16 inputs, fp32 accumulate
__device__ __forceinline__ void mma_f16(float* d, const uint32_t* a, const uint32_t* b) {
    asm volatile(
        "mma.sync.aligned.m16n8k16.row.col.f32.f16.f16.f32 "
        "{%0,%1,%2,%3}, {%4,%5,%6,%7}, {%8,%9}, {%0,%1,%2,%3};"
        : "+f"(d[0]), "+f"(d[1]), "+f"(d[2]), "+f"(d[3])
        : "r"(a[0]), "r"(a[1]), "r"(a[2]), "r"(a[3]),
          "r"(b[0]), "r"(b[1]));
}

// ---------------------------------------------------------------------------
// FP16 tensor-core GEMM (NT): C[M,N] = A[M,K] @ B[N,K]^T (row-major, K contig)
// 128x128 block tile, BK=16 (one k16 MMA step per tile), 256 threads = 8
// warps (2x4), warp tile 64x32. Double-buffered smem (packed half pairs),
// register prefetch of the next k-tile. Smem row stride GS=9 u32 ->
// conflict-free fragment loads (row*9+tig distinct mod 32).
// ---------------------------------------------------------------------------
#define GS 9

__device__ __forceinline__ void hgemm_body(uint32_t* As, uint32_t* Bs,
                                           const float* __restrict__ A,
                                           const float* __restrict__ B,
                                           float* __restrict__ C, int N, int K)
{
    const int tid  = threadIdx.x;
    const int lane = tid & 31;
    const int warp = tid >> 5;
    const int g    = lane >> 2;
    const int tig  = lane & 3;
    const int warp_m = warp >> 2;        // 0..1 -> m offset *64
    const int warp_n = warp & 3;         // 0..3 -> n offset *32
    const int bm = blockIdx.y;
    const int bn = blockIdx.x;

    const float* Ab = A + (size_t)bm * 128 * K;
    const float* Bb = B + (size_t)bn * 128 * K;

    // per-thread load coordinates (2 float4 each for A and B)
    int lrow[2], lks[2];
#pragma unroll
    for (int r = 0; r < 2; r++) {
        int e = tid + 256 * r;
        lrow[r] = e >> 2;
        lks[r]  = (e & 3) << 2;
    }

    float acc[4][4][4];
#pragma unroll
    for (int i = 0; i < 4; i++)
#pragma unroll
        for (int j = 0; j < 4; j++)
#pragma unroll
            for (int r = 0; r < 4; r++) acc[i][j][r] = 0.f;

    const int T = K / 16;
    float4 pa[2], pb[2];

    // prologue: prefetch tile 0
#pragma unroll
    for (int r = 0; r < 2; r++) {
        pa[r] = *(const float4*)(Ab + (size_t)lrow[r] * K + lks[r]);
        pb[r] = *(const float4*)(Bb + (size_t)lrow[r] * K + lks[r]);
    }

    for (int t = 0; t < T; t++) {
        const int buf = t & 1;
        uint32_t* Ad = As + buf * 128 * GS;
        uint32_t* Bd = Bs + buf * 128 * GS;
        // store prefetched tile into smem (packed half pairs)
#pragma unroll
        for (int r = 0; r < 2; r++) {
            uint32_t* ap = Ad + lrow[r] * GS + (lks[r] >> 1);
            ap[0] = packh2(pa[r].x, pa[r].y);
            ap[1] = packh2(pa[r].z, pa[r].w);
            uint32_t* bp = Bd + lrow[r] * GS + (lks[r] >> 1);
            bp[0] = packh2(pb[r].x, pb[r].y);
            bp[1] = packh2(pb[r].z, pb[r].w);
        }
        __syncthreads();

        // prefetch next tile while computing
        if (t + 1 < T) {
            int k0 = (t + 1) * 16;
#pragma unroll
            for (int r = 0; r < 2; r++) {
                pa[r] = *(const float4*)(Ab + (size_t)lrow[r] * K + k0 + lks[r]);
                pb[r] = *(const float4*)(Bb + (size_t)lrow[r] * K + k0 + lks[r]);
            }
        }

        uint32_t afr[4][4], bfr[4][2];
#pragma unroll
        for (int i = 0; i < 4; i++) {
            int row = warp_m * 64 + i * 16;
            afr[i][0] = Ad[(row + g)     * GS + tig];
            afr[i][1] = Ad[(row + g + 8) * GS + tig];
            afr[i][2] = Ad[(row + g)     * GS + tig + 4];
            afr[i][3] = Ad[(row + g + 8) * GS + tig + 4];
        }
#pragma unroll
        for (int j = 0; j < 4; j++) {
            int col = warp_n * 32 + j * 8;
            bfr[j][0] = Bd[(col + g) * GS + tig];
            bfr[j][1] = Bd[(col + g) * GS + tig + 4];
        }
#pragma unroll
        for (int i = 0; i < 4; i++)
#pragma unroll
            for (int j = 0; j < 4; j++)
                mma_f16(acc[i][j], afr[i], bfr[j]);
    }

    // epilogue
#pragma unroll
    for (int i = 0; i < 4; i++) {
        int row0 = bm * 128 + warp_m * 64 + i * 16 + g;
#pragma unroll
        for (int j = 0; j < 4; j++) {
            int col = bn * 128 + warp_n * 32 + j * 8 + 2 * tig;
            *(float2*)(C + (size_t)row0 * N + col)       = make_float2(acc[i][j][0], acc[i][j][1]);
            *(float2*)(C + (size_t)(row0 + 8) * N + col) = make_float2(acc[i][j][2], acc[i][j][3]);
        }
    }
}

__global__ __launch_bounds__(256, 2)
void hgemm_one(const float* __restrict__ A, const float* __restrict__ B,
               float* __restrict__ C, int N, int K)
{
    __shared__ uint32_t As[2 * 128 * GS];
    __shared__ uint32_t Bs[2 * 128 * GS];
    hgemm_body(As, Bs, A, B, C, N, K);
}

// K and V projections merged: blockIdx.z selects weight/output pair.
__global__ __launch_bounds__(256, 2)
void hgemm_kv(const float* __restrict__ x,
              const float* __restrict__ Wk, const float* __restrict__ Wv,
              float* __restrict__ Kp, float* __restrict__ Vp)
{
    __shared__ uint32_t As[2 * 128 * GS];
    __shared__ uint32_t Bs[2 * 128 * GS];
    if (blockIdx.z == 0) hgemm_body(As, Bs, x, Wk, Kp, PKV * PHD, PD);
    else                 hgemm_body(As, Bs, x, Wv, Vp, PKV * PHD, PD);
}

// ---------------------------------------------------------------------------
// RoPE (in place).  X viewed as (PM, nheads, 64); pairs (d, d+32), d<32.
// ---------------------------------------------------------------------------
__global__ void rope_kernel(float* __restrict__ X, const float* __restrict__ cs,
                            const float* __restrict__ sn, int nheads)
{
    int i = blockIdx.x * blockDim.x + threadIdx.x;
    int total = PM * nheads * 32;
    if (i >= total) return;
    int d   = i & 31;
    int h   = (i >> 5) % nheads;
    int row = i / (32 * nheads);
    int s   = row & (PS - 1);
    float c = cs[s * 32 + d];
    float sv = sn[s * 32 + d];
    float* base = X + ((size_t)row * nheads + h) * 64;
    float x1 = base[d];
    float x2 = base[d + 32];
    base[d]      = x1 * c - x2 * sv;
    base[d + 32] = x1 * sv + x2 * c;
}

// ---------------------------------------------------------------------------
// Causal flash attention, fp16 tensor cores.
// grid (S/64, H, B), 256 threads = 8 warps (4x2).
// Q/K half [row][d] pairs along d; V stored TRANSPOSED half [d][key] pairs
// along key; scores fp32 in smem; P written back as packed half pairs.
// ASH=36 u32 stride: fragment loads conflict-free (row*4+tig mod 32).
// ---------------------------------------------------------------------------
#define ASH 36
#define SSP 68
#define FA_SMEM (4 * 64 * ASH * 4 + 64 * SSP * 4 + 3 * 64 * 4)

__global__ __launch_bounds__(256, 2)
void flash_attn_h(const float* __restrict__ Q, const float* __restrict__ Kg,
                  const float* __restrict__ Vg, float* __restrict__ AO)
{
    extern __shared__ char smb[];
    uint32_t* Qh = (uint32_t*)smb;                 // [64][ASH] half pairs (d)
    uint32_t* Kh = Qh + 64 * ASH;                  // [64][ASH] half pairs (d)
    uint32_t* Vt = Kh + 64 * ASH;                  // [d][ASH]  half pairs (key)
    uint32_t* Ps = Vt + 64 * ASH;                  // [64][ASH] half pairs (key)
    float* Ssf   = (float*)(Ps + 64 * ASH);        // [64][SSP] fp32 scores
    float* row_m = Ssf + 64 * SSP;
    float* row_l = row_m + 64;
    float* row_a = row_l + 64;

    const int qt = blockIdx.x;
    const int h  = blockIdx.y;
    const int b  = blockIdx.z;
    const int kvh = h >> 2;
    const int tid  = threadIdx.x;
    const int lane = tid & 31;
    const int warp = tid >> 5;
    const int g    = lane >> 2;
    const int tig  = lane & 3;
    const int warp_m = warp >> 1;    // 0..3 -> 16 rows each
    const int warp_n = warp & 1;     // 0..1 -> 32 cols each

    const float* Qbase = Q + ((size_t)(b * PS + qt * 64)) * (PH * PHD) + h * PHD;

    // load Q tile -> half pairs [row][d]
#pragma unroll
    for (int r = 0; r < 4; r++) {
        int e   = tid + 256 * r;
        int row = e >> 4;
        int ds  = (e & 15) << 2;
        float4 v = *(const float4*)(Qbase + (size_t)row * (PH * PHD) + ds);
        uint32_t* qp = Qh + row * ASH + (ds >> 1);
        qp[0] = packh2(v.x, v.y);
        qp[1] = packh2(v.z, v.w);
    }
    if (tid < 64) { row_m[tid] = -1e30f; row_l[tid] = 0.f; }

    float o[4][4];   // [n-subtile][reg]: rows g,g+8 x col pairs
#pragma unroll
    for (int j = 0; j < 4; j++)
#pragma unroll
        for (int r = 0; r < 4; r++) o[j][r] = 0.f;

    const int rowbase = warp_m * 16;
    const int colbase = warp_n * 32;

    for (int kt = 0; kt <= qt; kt++) {
        const float* Kbase = Kg + ((size_t)(b * PS + kt * 64)) * (PKV * PHD) + kvh * PHD;
        const float* Vbase = Vg + ((size_t)(b * PS + kt * 64)) * (PKV * PHD) + kvh * PHD;

        __syncthreads();   // prior PV reads of Ps/Vt done; Qh stores done (iter 0)

        // K tile -> half pairs [key][d]
#pragma unroll
        for (int r = 0; r < 4; r++) {
            int e   = tid + 256 * r;
            int row = e >> 4;
            int ds  = (e & 15) << 2;
            float4 kv = *(const float4*)(Kbase + (size_t)row * (PKV * PHD) + ds);
            uint32_t* kp = Kh + row * ASH + (ds >> 1);
            kp[0] = packh2(kv.x, kv.y);
            kp[1] = packh2(kv.z, kv.w);
        }
        // V tile -> TRANSPOSED half pairs Vt[d][key]
#pragma unroll
        for (int r = 0; r < 2; r++) {
            int e    = tid + 256 * r;       // 0..511
            int a2   = e >> 4;              // 0..31 -> keys 2a2, 2a2+1
            int dcol = (e & 15) << 2;       // 0,4,...,60
            const float* r0p = Vbase + (size_t)(2 * a2) * (PKV * PHD) + dcol;
            float4 v0 = *(const float4*)r0p;
            float4 v1 = *(const float4*)(r0p + PKV * PHD);
            Vt[(dcol + 0) * ASH + a2] = packh2(v0.x, v1.x);
            Vt[(dcol + 1) * ASH + a2] = packh2(v0.y, v1.y);
            Vt[(dcol + 2) * ASH + a2] = packh2(v0.z, v1.z);
            Vt[(dcol + 3) * ASH + a2] = packh2(v0.w, v1.w);
        }
        __syncthreads();

        // S = Q @ K^T : warp tile 16 rows x 32 cols, k = d = 64 (4 k16 steps)
        float s_[4][4];
#pragma unroll
        for (int j = 0; j < 4; j++)
#pragma unroll
            for (int r = 0; r < 4; r++) s_[j][r] = 0.f;

#pragma unroll
        for (int ks = 0; ks < 64; ks += 16) {
            const int ko = ks >> 1;
            uint32_t afr[4], bfr[4][2];
            afr[0] = Qh[(rowbase + g)     * ASH + ko + tig];
            afr[1] = Qh[(rowbase + g + 8) * ASH + ko + tig];
            afr[2] = Qh[(rowbase + g)     * ASH + ko + tig + 4];
            afr[3] = Qh[(rowbase + g + 8) * ASH + ko + tig + 4];
#pragma unroll
            for (int j = 0; j < 4; j++) {
                int col = colbase + j * 8;
                bfr[j][0] = Kh[(col + g) * ASH + ko + tig];
                bfr[j][1] = Kh[(col + g) * ASH + ko + tig + 4];
            }
#pragma unroll
            for (int j = 0; j < 4; j++)
                mma_f16(s_[j], afr, bfr[j]);
        }

        // scale + causal mask, write fp32 scores
        const int qr0 = qt * 64 + rowbase + g;
#pragma unroll
        for (int j = 0; j < 4; j++) {
            int c0 = colbase + j * 8 + 2 * tig;
            int kc0 = kt * 64 + c0;
            float v0 = s_[j][0] * 0.125f, v1 = s_[j][1] * 0.125f;
            float v2 = s_[j][2] * 0.125f, v3 = s_[j][3] * 0.125f;
            if (kc0     > qr0)     v0 = -1e30f;
            if (kc0 + 1 > qr0)     v1 = -1e30f;
            if (kc0     > qr0 + 8) v2 = -1e30f;
            if (kc0 + 1 > qr0 + 8) v3 = -1e30f;
            *(float2*)&Ssf[(rowbase + g)     * SSP + c0] = make_float2(v0, v1);
            *(float2*)&Ssf[(rowbase + g + 8) * SSP + c0] = make_float2(v2, v3);
        }
        __syncthreads();

        // online softmax: 64 rows x 4 threads, 16 keys each; P -> half pairs
        {
            const int row = tid >> 2;
            const int p   = tid & 3;
            float* Pr = Ssf + row * SSP + p * 16;
            float mx = -1e30f;
#pragma unroll
            for (int n = 0; n < 16; n++) mx = fmaxf(mx, Pr[n]);
            mx = fmaxf(mx, __shfl_xor_sync(0xffffffffu, mx, 1));
            mx = fmaxf(mx, __shfl_xor_sync(0xffffffffu, mx, 2));
            float mold = row_m[row];
            float newm = fmaxf(mold, mx);
            float ssum = 0.f;
            uint32_t* Pu = Ps + row * ASH + p * 8;
#pragma unroll
            for (int n = 0; n < 8; n++) {
                float ea = __expf(Pr[2 * n]     - newm);
                float eb = __expf(Pr[2 * n + 1] - newm);
                ssum += ea + eb;
                Pu[n] = packh2(ea, eb);
            }
            ssum += __shfl_xor_sync(0xffffffffu, ssum, 1);
            ssum += __shfl_xor_sync(0xffffffffu, ssum, 2);
            if (p == 0) {
                float alpha = __expf(mold - newm);
                row_m[row] = newm;
                row_l[row] = row_l[row] * alpha + ssum;
                row_a[row] = alpha;
            }
        }
        __syncthreads();

        // O = O*alpha + P @ V   (k = 64 keys, 4 k16 steps)
        float al0 = row_a[rowbase + g];
        float al1 = row_a[rowbase + g + 8];
#pragma unroll
        for (int j = 0; j < 4; j++) {
            o[j][0] *= al0; o[j][1] *= al0;
            o[j][2] *= al1; o[j][3] *= al1;
        }
#pragma unroll
        for (int ks = 0; ks < 64; ks += 16) {
            const int ko = ks >> 1;
            uint32_t afr[4], bfr[4][2];
            afr[0] = Ps[(rowbase + g)     * ASH + ko + tig];
            afr[1] = Ps[(rowbase + g + 8) * ASH + ko + tig];
            afr[2] = Ps[(rowbase + g)     * ASH + ko + tig + 4];
            afr[3] = Ps[(rowbase + g + 8) * ASH + ko + tig + 4];
#pragma unroll
            for (int j = 0; j < 4; j++) {
                int col = colbase + j * 8;
                bfr[j][0] = Vt[(col + g) * ASH + ko + tig];
                bfr[j][1] = Vt[(col + g) * ASH + ko + tig + 4];
            }
#pragma unroll
            for (int j = 0; j < 4; j++)
                mma_f16(o[j], afr, bfr[j]);
        }
    }

    // epilogue: normalize and store
    float il0 = 1.0f / row_l[rowbase + g];
    float il1 = 1.0f / row_l[rowbase + g + 8];
    float* Ob = AO + ((size_t)(b * PS + qt * 64)) * (PH * PHD) + h * PHD;
    const int r0 = rowbase + g;
#pragma unroll
    for (int j = 0; j < 4; j++) {
        int c0 = colbase + j * 8 + 2 * tig;
        *(float2*)(Ob + (size_t)r0 * (PH * PHD) + c0) =
            make_float2(o[j][0] * il0, o[j][1] * il0);
        *(float2*)(Ob + (size_t)(r0 + 8) * (PH * PHD) + c0) =
            make_float2(o[j][2] * il1, o[j][3] * il1);
    }
}

// ---------------------------------------------------------------------------
// Launch
// ---------------------------------------------------------------------------
extern "C" void kernel_launch(void* const* d_in, const int* in_sizes, int n_in,
                              void* d_out, int out_size)
{
    (void)in_sizes; (void)n_in; (void)out_size;
    const float* x  = (const float*)d_in[0];
    const float* cs = (const float*)d_in[1];
    const float* sn = (const float*)d_in[2];
    const float* Wq = (const float*)d_in[3];
    const float* Wk = (const float*)d_in[4];
    const float* Wv = (const float*)d_in[5];
    const float* Wo = (const float*)d_in[6];
    float* out = (float*)d_out;

    float *Qp, *Kp, *Vp, *AOp;
    cudaGetSymbolAddress((void**)&Qp, g_Q);
    cudaGetSymbolAddress((void**)&Kp, g_K);
    cudaGetSymbolAddress((void**)&Vp, g_V);
    cudaGetSymbolAddress((void**)&AOp, g_AO);

    cudaFuncSetAttribute(flash_attn_h, cudaFuncAttributeMaxDynamicSharedMemorySize, FA_SMEM);

    // QKV projections (fp16 tensor cores, double-buffered)
    hgemm_one<<<dim3(PD / 128, PM / 128), 256>>>(x, Wq, Qp, PD, PD);
    hgemm_kv<<<dim3((PKV * PHD) / 128, PM / 128, 2), 256>>>(x, Wk, Wv, Kp, Vp);

    // RoPE on Q and K
    rope_kernel<<<(PM * PH * 32) / 256, 256>>>(Qp, cs, sn, PH);
    rope_kernel<<<(PM * PKV * 32) / 256, 256>>>(Kp, cs, sn, PKV);

    // causal flash attention (fp16 tensor cores)
    flash_attn_h<<<dim3(PS / 64, PH, PB), 256, FA_SMEM>>>(Qp, Kp, Vp, AOp);

    // output projection (fp16 tensor cores)
    hgemm_one<<<dim3(PD / 128, PM / 128), 256>>>(AOp, Wo, out, PD, PD);
}

// round 12
// speedup vs baseline: 2.3060x; 1.2349x over previous
#include <cuda_runtime.h>
#include <cuda_fp16.h>
#include <cstdint>
#include <cstdio>

// Problem constants
#define PB 2
#define PS 2048
#define PD 2048
#define PH 32
#define PKV 8
#define PHD 64
#define PM (PB * PS)          // 4096 rows of x
#define PG (PH / PKV)         // 4

// ---------------------------------------------------------------------------
// Scratch (device globals; no runtime allocation allowed)
// ---------------------------------------------------------------------------
__device__ float g_Q[(size_t)PM * PD];             // (4096, 2048)  32MB
__device__ float g_K[(size_t)PM * (PKV * PHD)];    // (4096, 512)    8MB
__device__ float g_V[(size_t)PM * (PKV * PHD)];    // (4096, 512)    8MB
__device__ float g_AO[(size_t)PM * PD];            // (4096, 2048)  32MB

// ---------------------------------------------------------------------------
// fp16 helpers
// ---------------------------------------------------------------------------
__device__ __forceinline__ uint32_t packh2(float lo, float hi) {
    __half2 h = __floats2half2_rn(lo, hi);   // lo -> low 16 bits
    return *(uint32_t*)&h;
}

// mma.m16n8k16 fp16 inputs, fp32 accumulate
__device__ __forceinline__ void mma_f16(float* d, const uint32_t* a, const uint32_t* b) {
    asm volatile(
        "mma.sync.aligned.m16n8k16.row.col.f32.f16.f16.f32 "
        "{%0,%1,%2,%3}, {%4,%5,%6,%7}, {%8,%9}, {%0,%1,%2,%3};"
        : "+f"(d[0]), "+f"(d[1]), "+f"(d[2]), "+f"(d[3])
        : "r"(a[0]), "r"(a[1]), "r"(a[2]), "r"(a[3]),
          "r"(b[0]), "r"(b[1]));
}

// ---------------------------------------------------------------------------
// FP16 tensor-core GEMM (NT), unchanged from R11 (known good).
// 128x128 block tile, BK=16, 256 threads = 8 warps (2x4), warp tile 64x32.
// ---------------------------------------------------------------------------
#define GS 9

__device__ __forceinline__ void hgemm_body(uint32_t* As, uint32_t* Bs,
                                           const float* __restrict__ A,
                                           const float* __restrict__ B,
                                           float* __restrict__ C, int N, int K)
{
    const int tid  = threadIdx.x;
    const int lane = tid & 31;
    const int warp = tid >> 5;
    const int g    = lane >> 2;
    const int tig  = lane & 3;
    const int warp_m = warp >> 2;
    const int warp_n = warp & 3;
    const int bm = blockIdx.y;
    const int bn = blockIdx.x;

    const float* Ab = A + (size_t)bm * 128 * K;
    const float* Bb = B + (size_t)bn * 128 * K;

    int lrow[2], lks[2];
#pragma unroll
    for (int r = 0; r < 2; r++) {
        int e = tid + 256 * r;
        lrow[r] = e >> 2;
        lks[r]  = (e & 3) << 2;
    }

    float acc[4][4][4];
#pragma unroll
    for (int i = 0; i < 4; i++)
#pragma unroll
        for (int j = 0; j < 4; j++)
#pragma unroll
            for (int r = 0; r < 4; r++) acc[i][j][r] = 0.f;

    const int T = K / 16;
    float4 pa[2], pb[2];

#pragma unroll
    for (int r = 0; r < 2; r++) {
        pa[r] = *(const float4*)(Ab + (size_t)lrow[r] * K + lks[r]);
        pb[r] = *(const float4*)(Bb + (size_t)lrow[r] * K + lks[r]);
    }

    for (int t = 0; t < T; t++) {
        const int buf = t & 1;
        uint32_t* Ad = As + buf * 128 * GS;
        uint32_t* Bd = Bs + buf * 128 * GS;
#pragma unroll
        for (int r = 0; r < 2; r++) {
            uint32_t* ap = Ad + lrow[r] * GS + (lks[r] >> 1);
            ap[0] = packh2(pa[r].x, pa[r].y);
            ap[1] = packh2(pa[r].z, pa[r].w);
            uint32_t* bp = Bd + lrow[r] * GS + (lks[r] >> 1);
            bp[0] = packh2(pb[r].x, pb[r].y);
            bp[1] = packh2(pb[r].z, pb[r].w);
        }
        __syncthreads();

        if (t + 1 < T) {
            int k0 = (t + 1) * 16;
#pragma unroll
            for (int r = 0; r < 2; r++) {
                pa[r] = *(const float4*)(Ab + (size_t)lrow[r] * K + k0 + lks[r]);
                pb[r] = *(const float4*)(Bb + (size_t)lrow[r] * K + k0 + lks[r]);
            }
        }

        uint32_t afr[4][4], bfr[4][2];
#pragma unroll
        for (int i = 0; i < 4; i++) {
            int row = warp_m * 64 + i * 16;
            afr[i][0] = Ad[(row + g)     * GS + tig];
            afr[i][1] = Ad[(row + g + 8) * GS + tig];
            afr[i][2] = Ad[(row + g)     * GS + tig + 4];
            afr[i][3] = Ad[(row + g + 8) * GS + tig + 4];
        }
#pragma unroll
        for (int j = 0; j < 4; j++) {
            int col = warp_n * 32 + j * 8;
            bfr[j][0] = Bd[(col + g) * GS + tig];
            bfr[j][1] = Bd[(col + g) * GS + tig + 4];
        }
#pragma unroll
        for (int i = 0; i < 4; i++)
#pragma unroll
            for (int j = 0; j < 4; j++)
                mma_f16(acc[i][j], afr[i], bfr[j]);
    }

#pragma unroll
    for (int i = 0; i < 4; i++) {
        int row0 = bm * 128 + warp_m * 64 + i * 16 + g;
#pragma unroll
        for (int j = 0; j < 4; j++) {
            int col = bn * 128 + warp_n * 32 + j * 8 + 2 * tig;
            *(float2*)(C + (size_t)row0 * N + col)       = make_float2(acc[i][j][0], acc[i][j][1]);
            *(float2*)(C + (size_t)(row0 + 8) * N + col) = make_float2(acc[i][j][2], acc[i][j][3]);
        }
    }
}

__global__ __launch_bounds__(256, 2)
void hgemm_one(const float* __restrict__ A, const float* __restrict__ B,
               float* __restrict__ C, int N, int K)
{
    __shared__ uint32_t As[2 * 128 * GS];
    __shared__ uint32_t Bs[2 * 128 * GS];
    hgemm_body(As, Bs, A, B, C, N, K);
}

__global__ __launch_bounds__(256, 2)
void hgemm_kv(const float* __restrict__ x,
              const float* __restrict__ Wk, const float* __restrict__ Wv,
              float* __restrict__ Kp, float* __restrict__ Vp)
{
    __shared__ uint32_t As[2 * 128 * GS];
    __shared__ uint32_t Bs[2 * 128 * GS];
    if (blockIdx.z == 0) hgemm_body(As, Bs, x, Wk, Kp, PKV * PHD, PD);
    else                 hgemm_body(As, Bs, x, Wv, Vp, PKV * PHD, PD);
}

// ---------------------------------------------------------------------------
// RoPE (in place).
// ---------------------------------------------------------------------------
__global__ void rope_kernel(float* __restrict__ X, const float* __restrict__ cs,
                            const float* __restrict__ sn, int nheads)
{
    int i = blockIdx.x * blockDim.x + threadIdx.x;
    int total = PM * nheads * 32;
    if (i >= total) return;
    int d   = i & 31;
    int h   = (i >> 5) % nheads;
    int row = i / (32 * nheads);
    int s   = row & (PS - 1);
    float c = cs[s * 32 + d];
    float sv = sn[s * 32 + d];
    float* base = X + ((size_t)row * nheads + h) * 64;
    float x1 = base[d];
    float x2 = base[d + 32];
    base[d]      = x1 * c - x2 * sv;
    base[d + 32] = x1 * sv + x2 * c;
}

// ---------------------------------------------------------------------------
// Causal flash attention, fp16 MMA, register-resident softmax (FA2 style).
// grid (S/128, H, B), 256 threads = 8 warps; warp w owns rows [16w,16w+16)
// of a 128-query tile, all 64 key-columns. S/P never touch smem; row stats
// reduced over the 4 tig-lanes via shfl. K[key][d] and V^T[d][key] in smem.
// ---------------------------------------------------------------------------
#define ASH 36

__global__ __launch_bounds__(256, 2)
void flash_attn_reg(const float* __restrict__ Q, const float* __restrict__ Kg,
                    const float* __restrict__ Vg, float* __restrict__ AO)
{
    __shared__ uint32_t Kh[64 * ASH];   // [key][d-pairs]
    __shared__ uint32_t Vt[64 * ASH];   // [d][key-pairs]

    const int qt = blockIdx.x;
    const int h  = blockIdx.y;
    const int b  = blockIdx.z;
    const int kvh = h >> 2;
    const int tid  = threadIdx.x;
    const int lane = tid & 31;
    const int warp = tid >> 5;
    const int g    = lane >> 2;
    const int tig  = lane & 3;
    const int qr0  = qt * 128 + warp * 16 + g;    // global query row (row0)

    // Q fragments (held in registers for the whole kernel)
    uint32_t qfr[4][4];
    const float* Qr0 = Q + ((size_t)(b * PS) + qr0) * (PH * PHD) + h * PHD;
    const float* Qr8 = Qr0 + 8 * (PH * PHD);
#pragma unroll
    for (int s = 0; s < 4; s++) {
        float2 x0 = *(const float2*)(Qr0 + s * 16 + 2 * tig);
        float2 x8 = *(const float2*)(Qr8 + s * 16 + 2 * tig);
        float2 y0 = *(const float2*)(Qr0 + s * 16 + 8 + 2 * tig);
        float2 y8 = *(const float2*)(Qr8 + s * 16 + 8 + 2 * tig);
        qfr[s][0] = packh2(x0.x, x0.y);
        qfr[s][1] = packh2(x8.x, x8.y);
        qfr[s][2] = packh2(y0.x, y0.y);
        qfr[s][3] = packh2(y8.x, y8.y);
    }

    float o[8][4];
#pragma unroll
    for (int j = 0; j < 8; j++)
#pragma unroll
        for (int r = 0; r < 4; r++) o[j][r] = 0.f;
    float m0 = -1e30f, m1 = -1e30f, l0 = 0.f, l1 = 0.f;

    const int ktmax = 2 * qt + 1;
    for (int kt = 0; kt <= ktmax; kt++) {
        const float* Kbase = Kg + ((size_t)(b * PS + kt * 64)) * (PKV * PHD) + kvh * PHD;
        const float* Vbase = Vg + ((size_t)(b * PS + kt * 64)) * (PKV * PHD) + kvh * PHD;

        __syncthreads();   // previous tile's smem reads complete

        // K tile -> Kh[key][d-pairs]
#pragma unroll
        for (int r = 0; r < 4; r++) {
            int e   = tid + 256 * r;
            int row = e >> 4;
            int ds  = (e & 15) << 2;
            float4 kv = *(const float4*)(Kbase + (size_t)row * (PKV * PHD) + ds);
            uint32_t* kp = Kh + row * ASH + (ds >> 1);
            kp[0] = packh2(kv.x, kv.y);
            kp[1] = packh2(kv.z, kv.w);
        }
        // V tile -> transposed Vt[d][key-pairs]
#pragma unroll
        for (int r = 0; r < 2; r++) {
            int e    = tid + 256 * r;
            int a2   = e >> 4;
            int dcol = (e & 15) << 2;
            const float* r0p = Vbase + (size_t)(2 * a2) * (PKV * PHD) + dcol;
            float4 v0 = *(const float4*)r0p;
            float4 v1 = *(const float4*)(r0p + PKV * PHD);
            Vt[(dcol + 0) * ASH + a2] = packh2(v0.x, v1.x);
            Vt[(dcol + 1) * ASH + a2] = packh2(v0.y, v1.y);
            Vt[(dcol + 2) * ASH + a2] = packh2(v0.z, v1.z);
            Vt[(dcol + 3) * ASH + a2] = packh2(v0.w, v1.w);
        }
        __syncthreads();

        // warp entirely above the diagonal? (all keys > all its queries)
        if (kt * 64 > qt * 128 + warp * 16 + 15) continue;

        // S = Q @ K^T : 16 rows x 64 cols in registers
        float s_[8][4];
#pragma unroll
        for (int j = 0; j < 8; j++)
#pragma unroll
            for (int r = 0; r < 4; r++) s_[j][r] = 0.f;

#pragma unroll
        for (int s4 = 0; s4 < 4; s4++) {
#pragma unroll
            for (int j = 0; j < 8; j++) {
                uint32_t bfr[2];
                bfr[0] = Kh[(8 * j + g) * ASH + 8 * s4 + tig];
                bfr[1] = Kh[(8 * j + g) * ASH + 8 * s4 + tig + 4];
                mma_f16(s_[j], qfr[s4], bfr);
            }
        }

        // scale + causal mask
        const bool tail = (kt * 64 + 63 > qr0);
#pragma unroll
        for (int j = 0; j < 8; j++) {
            s_[j][0] *= 0.125f; s_[j][1] *= 0.125f;
            s_[j][2] *= 0.125f; s_[j][3] *= 0.125f;
            if (tail) {
                int kc = kt * 64 + 8 * j + 2 * tig;
                if (kc     > qr0)     s_[j][0] = -1e30f;
                if (kc + 1 > qr0)     s_[j][1] = -1e30f;
                if (kc     > qr0 + 8) s_[j][2] = -1e30f;
                if (kc + 1 > qr0 + 8) s_[j][3] = -1e30f;
            }
        }

        // register online softmax (rows g and g+8; 4 tig-lanes share a row)
        float mx0 = -1e30f, mx1 = -1e30f;
#pragma unroll
        for (int j = 0; j < 8; j++) {
            mx0 = fmaxf(mx0, fmaxf(s_[j][0], s_[j][1]));
            mx1 = fmaxf(mx1, fmaxf(s_[j][2], s_[j][3]));
        }
        mx0 = fmaxf(mx0, __shfl_xor_sync(0xffffffffu, mx0, 1));
        mx0 = fmaxf(mx0, __shfl_xor_sync(0xffffffffu, mx0, 2));
        mx1 = fmaxf(mx1, __shfl_xor_sync(0xffffffffu, mx1, 1));
        mx1 = fmaxf(mx1, __shfl_xor_sync(0xffffffffu, mx1, 2));

        float nm0 = fmaxf(m0, mx0), nm1 = fmaxf(m1, mx1);
        float al0 = __expf(m0 - nm0), al1 = __expf(m1 - nm1);
        float sum0 = 0.f, sum1 = 0.f;
        uint32_t pf[4][4];
#pragma unroll
        for (int s4 = 0; s4 < 4; s4++) {
#pragma unroll
            for (int jj = 0; jj < 2; jj++) {
                int j = 2 * s4 + jj;
                float p0 = __expf(s_[j][0] - nm0);
                float p1 = __expf(s_[j][1] - nm0);
                float p2 = __expf(s_[j][2] - nm1);
                float p3 = __expf(s_[j][3] - nm1);
                sum0 += p0 + p1;
                sum1 += p2 + p3;
                pf[s4][2 * jj + 0] = packh2(p0, p1);
                pf[s4][2 * jj + 1] = packh2(p2, p3);
            }
        }
        sum0 += __shfl_xor_sync(0xffffffffu, sum0, 1);
        sum0 += __shfl_xor_sync(0xffffffffu, sum0, 2);
        sum1 += __shfl_xor_sync(0xffffffffu, sum1, 1);
        sum1 += __shfl_xor_sync(0xffffffffu, sum1, 2);

        l0 = l0 * al0 + sum0;
        l1 = l1 * al1 + sum1;
        m0 = nm0; m1 = nm1;

#pragma unroll
        for (int j = 0; j < 8; j++) {
            o[j][0] *= al0; o[j][1] *= al0;
            o[j][2] *= al1; o[j][3] *= al1;
        }

        // O += P @ V  (B fragments from transposed V)
#pragma unroll
        for (int s4 = 0; s4 < 4; s4++) {
#pragma unroll
            for (int j = 0; j < 8; j++) {
                uint32_t bfr[2];
                bfr[0] = Vt[(8 * j + g) * ASH + 8 * s4 + tig];
                bfr[1] = Vt[(8 * j + g) * ASH + 8 * s4 + tig + 4];
                mma_f16(o[j], pf[s4], bfr);
            }
        }
    }

    // epilogue: normalize + store
    float il0 = 1.0f / l0;
    float il1 = 1.0f / l1;
    float* Ob = AO + ((size_t)(b * PS) + qr0) * (PH * PHD) + h * PHD;
#pragma unroll
    for (int j = 0; j < 8; j++) {
        int c0 = 8 * j + 2 * tig;
        *(float2*)(Ob + c0) = make_float2(o[j][0] * il0, o[j][1] * il0);
        *(float2*)(Ob + 8 * (PH * PHD) + c0) = make_float2(o[j][2] * il1, o[j][3] * il1);
    }
}

// ---------------------------------------------------------------------------
// Launch
// ---------------------------------------------------------------------------
extern "C" void kernel_launch(void* const* d_in, const int* in_sizes, int n_in,
                              void* d_out, int out_size)
{
    (void)in_sizes; (void)n_in; (void)out_size;
    const float* x  = (const float*)d_in[0];
    const float* cs = (const float*)d_in[1];
    const float* sn = (const float*)d_in[2];
    const float* Wq = (const float*)d_in[3];
    const float* Wk = (const float*)d_in[4];
    const float* Wv = (const float*)d_in[5];
    const float* Wo = (const float*)d_in[6];
    float* out = (float*)d_out;

    float *Qp, *Kp, *Vp, *AOp;
    cudaGetSymbolAddress((void**)&Qp, g_Q);
    cudaGetSymbolAddress((void**)&Kp, g_K);
    cudaGetSymbolAddress((void**)&Vp, g_V);
    cudaGetSymbolAddress((void**)&AOp, g_AO);

    // QKV projections (fp16 tensor cores, double-buffered)
    hgemm_one<<<dim3(PD / 128, PM / 128), 256>>>(x, Wq, Qp, PD, PD);
    hgemm_kv<<<dim3((PKV * PHD) / 128, PM / 128, 2), 256>>>(x, Wk, Wv, Kp, Vp);

    // RoPE on Q and K
    rope_kernel<<<(PM * PH * 32) / 256, 256>>>(Qp, cs, sn, PH);
    rope_kernel<<<(PM * PKV * 32) / 256, 256>>>(Kp, cs, sn, PKV);

    // causal flash attention (fp16, register softmax)
    flash_attn_reg<<<dim3(PS / 128, PH, PB), 256>>>(Qp, Kp, Vp, AOp);

    // output projection (fp16 tensor cores)
    hgemm_one<<<dim3(PD / 128, PM / 128), 256>>>(AOp, Wo, out, PD, PD);
}

// round 15
// speedup vs baseline: 2.3749x; 1.0299x over previous
#include <cuda_runtime.h>
#include <cuda_fp16.h>
#include <cstdint>
#include <cstdio>

// Problem constants
#define PB 2
#define PS 2048
#define PD 2048
#define PH 32
#define PKV 8
#define PHD 64
#define PM (PB * PS)          // 4096 rows of x
#define PG (PH / PKV)         // 4

// ---------------------------------------------------------------------------
// Scratch (device globals; no runtime allocation allowed)
// ---------------------------------------------------------------------------
__device__ float g_Q[(size_t)PM * PD];             // (4096, 2048)  32MB
__device__ float g_K[(size_t)PM * (PKV * PHD)];    // (4096, 512)    8MB
__device__ float g_V[(size_t)PM * (PKV * PHD)];    // (4096, 512)    8MB
__device__ float g_AO[(size_t)PM * PD];            // (4096, 2048)  32MB

// ---------------------------------------------------------------------------
// fp16 helpers
// ---------------------------------------------------------------------------
__device__ __forceinline__ uint32_t packh2(float lo, float hi) {
    __half2 h = __floats2half2_rn(lo, hi);   // lo -> low 16 bits
    return *(uint32_t*)&h;
}

// mma.m16n8k16 fp16 inputs, fp32 accumulate
__device__ __forceinline__ void mma_f16(float* d, const uint32_t* a, const uint32_t* b) {
    asm volatile(
        "mma.sync.aligned.m16n8k16.row.col.f32.f16.f16.f32 "
        "{%0,%1,%2,%3}, {%4,%5,%6,%7}, {%8,%9}, {%0,%1,%2,%3};"
        : "+f"(d[0]), "+f"(d[1]), "+f"(d[2]), "+f"(d[3])
        : "r"(a[0]), "r"(a[1]), "r"(a[2]), "r"(a[3]),
          "r"(b[0]), "r"(b[1]));
}

// ---------------------------------------------------------------------------
// FP16 tensor-core GEMM (NT) body, R11 core (known good), bn passed in.
// 128x128 block tile, BK=16, 256 threads = 8 warps (2x4), warp tile 64x32.
// ---------------------------------------------------------------------------
#define GS 9

__device__ __forceinline__ void hgemm_body(uint32_t* As, uint32_t* Bs, int bn,
                                           const float* __restrict__ A,
                                           const float* __restrict__ B,
                                           float* __restrict__ C, int N, int K)
{
    const int tid  = threadIdx.x;
    const int lane = tid & 31;
    const int warp = tid >> 5;
    const int g    = lane >> 2;
    const int tig  = lane & 3;
    const int warp_m = warp >> 2;
    const int warp_n = warp & 3;
    const int bm = blockIdx.y;

    const float* Ab = A + (size_t)bm * 128 * K;
    const float* Bb = B + (size_t)bn * 128 * K;

    int lrow[2], lks[2];
#pragma unroll
    for (int r = 0; r < 2; r++) {
        int e = tid + 256 * r;
        lrow[r] = e >> 2;
        lks[r]  = (e & 3) << 2;
    }

    float acc[4][4][4];
#pragma unroll
    for (int i = 0; i < 4; i++)
#pragma unroll
        for (int j = 0; j < 4; j++)
#pragma unroll
            for (int r = 0; r < 4; r++) acc[i][j][r] = 0.f;

    const int T = K / 16;
    float4 pa[2], pb[2];

#pragma unroll
    for (int r = 0; r < 2; r++) {
        pa[r] = *(const float4*)(Ab + (size_t)lrow[r] * K + lks[r]);
        pb[r] = *(const float4*)(Bb + (size_t)lrow[r] * K + lks[r]);
    }

    for (int t = 0; t < T; t++) {
        const int buf = t & 1;
        uint32_t* Ad = As + buf * 128 * GS;
        uint32_t* Bd = Bs + buf * 128 * GS;
#pragma unroll
        for (int r = 0; r < 2; r++) {
            uint32_t* ap = Ad + lrow[r] * GS + (lks[r] >> 1);
            ap[0] = packh2(pa[r].x, pa[r].y);
            ap[1] = packh2(pa[r].z, pa[r].w);
            uint32_t* bp = Bd + lrow[r] * GS + (lks[r] >> 1);
            bp[0] = packh2(pb[r].x, pb[r].y);
            bp[1] = packh2(pb[r].z, pb[r].w);
        }
        __syncthreads();

        if (t + 1 < T) {
            int k0 = (t + 1) * 16;
#pragma unroll
            for (int r = 0; r < 2; r++) {
                pa[r] = *(const float4*)(Ab + (size_t)lrow[r] * K + k0 + lks[r]);
                pb[r] = *(const float4*)(Bb + (size_t)lrow[r] * K + k0 + lks[r]);
            }
        }

        uint32_t afr[4][4], bfr[4][2];
#pragma unroll
        for (int i = 0; i < 4; i++) {
            int row = warp_m * 64 + i * 16;
            afr[i][0] = Ad[(row + g)     * GS + tig];
            afr[i][1] = Ad[(row + g + 8) * GS + tig];
            afr[i][2] = Ad[(row + g)     * GS + tig + 4];
            afr[i][3] = Ad[(row + g + 8) * GS + tig + 4];
        }
#pragma unroll
        for (int j = 0; j < 4; j++) {
            int col = warp_n * 32 + j * 8;
            bfr[j][0] = Bd[(col + g) * GS + tig];
            bfr[j][1] = Bd[(col + g) * GS + tig + 4];
        }
#pragma unroll
        for (int i = 0; i < 4; i++)
#pragma unroll
            for (int j = 0; j < 4; j++)
                mma_f16(acc[i][j], afr[i], bfr[j]);
    }

#pragma unroll
    for (int i = 0; i < 4; i++) {
        int row0 = bm * 128 + warp_m * 64 + i * 16 + g;
#pragma unroll
        for (int j = 0; j < 4; j++) {
            int col = bn * 128 + warp_n * 32 + j * 8 + 2 * tig;
            *(float2*)(C + (size_t)row0 * N + col)       = make_float2(acc[i][j][0], acc[i][j][1]);
            *(float2*)(C + (size_t)(row0 + 8) * N + col) = make_float2(acc[i][j][2], acc[i][j][3]);
        }
    }
}

// All three projections in ONE launch. grid (24, 32):
//   x in [0,16)  -> Q columns (N=2048)
//   x in [16,20) -> K columns (N=512)
//   x in [20,24) -> V columns (N=512)
__global__ __launch_bounds__(256, 2)
void hgemm_qkv(const float* __restrict__ x,
               const float* __restrict__ Wq, const float* __restrict__ Wk,
               const float* __restrict__ Wv,
               float* __restrict__ Qp, float* __restrict__ Kp,
               float* __restrict__ Vp)
{
    __shared__ uint32_t As[2 * 128 * GS];
    __shared__ uint32_t Bs[2 * 128 * GS];
    int bx = blockIdx.x;
    if (bx < 16)      hgemm_body(As, Bs, bx,      x, Wq, Qp, PD,        PD);
    else if (bx < 20) hgemm_body(As, Bs, bx - 16, x, Wk, Kp, PKV * PHD, PD);
    else              hgemm_body(As, Bs, bx - 20, x, Wv, Vp, PKV * PHD, PD);
}

__global__ __launch_bounds__(256, 2)
void hgemm_one(const float* __restrict__ A, const float* __restrict__ B,
               float* __restrict__ C, int N, int K)
{
    __shared__ uint32_t As[2 * 128 * GS];
    __shared__ uint32_t Bs[2 * 128 * GS];
    hgemm_body(As, Bs, blockIdx.x, A, B, C, N, K);
}

// ---------------------------------------------------------------------------
// RoPE (in place) — K only now (Q rope fused into attention).
// ---------------------------------------------------------------------------
__global__ void rope_kernel(float* __restrict__ X, const float* __restrict__ cs,
                            const float* __restrict__ sn, int nheads)
{
    int i = blockIdx.x * blockDim.x + threadIdx.x;
    int total = PM * nheads * 32;
    if (i >= total) return;
    int d   = i & 31;
    int h   = (i >> 5) % nheads;
    int row = i / (32 * nheads);
    int s   = row & (PS - 1);
    float c = cs[s * 32 + d];
    float sv = sn[s * 32 + d];
    float* base = X + ((size_t)row * nheads + h) * 64;
    float x1 = base[d];
    float x2 = base[d + 32];
    base[d]      = x1 * c - x2 * sv;
    base[d + 32] = x1 * sv + x2 * c;
}

// ---------------------------------------------------------------------------
// Causal flash attention, fp16 MMA, register-resident softmax (FA2 style),
// RoPE applied to Q at fragment-load time, heavy-tiles-first scheduling.
// grid (S/128, H, B), 256 threads = 8 warps; warp w owns rows [16w,16w+16).
// ---------------------------------------------------------------------------
#define ASH 36

__global__ __launch_bounds__(256, 2)
void flash_attn_reg(const float* __restrict__ Q, const float* __restrict__ Kg,
                    const float* __restrict__ Vg,
                    const float* __restrict__ cs, const float* __restrict__ sn,
                    float* __restrict__ AO)
{
    __shared__ uint32_t Kh[64 * ASH];   // [key][d-pairs]
    __shared__ uint32_t Vt[64 * ASH];   // [d][key-pairs]

    const int qt = (int)gridDim.x - 1 - (int)blockIdx.x;  // heavy tiles first
    const int h  = blockIdx.y;
    const int b  = blockIdx.z;
    const int kvh = h >> 2;
    const int tid  = threadIdx.x;
    const int lane = tid & 31;
    const int warp = tid >> 5;
    const int g    = lane >> 2;
    const int tig  = lane & 3;
    const int qr0  = qt * 128 + warp * 16 + g;    // query row (within seq)

    // Q fragments with fused RoPE. Pairs (d, d+32) map to blocks s <-> s+2.
    uint32_t qfr[4][4];
    {
        const float* Qr0 = Q + ((size_t)(b * PS) + qr0) * (PH * PHD) + h * PHD;
        const float* Qr8 = Qr0 + 8 * (PH * PHD);
        const float* cs0 = cs + (size_t)qr0 * 32;
        const float* sn0 = sn + (size_t)qr0 * 32;
        const float* cs8 = cs0 + 8 * 32;
        const float* sn8 = sn0 + 8 * 32;
#pragma unroll
        for (int s = 0; s < 2; s++) {
#pragma unroll
            for (int sub = 0; sub < 2; sub++) {
                int d = s * 16 + sub * 8 + 2 * tig;   // d in [0,32)
                float2 a0 = *(const float2*)(Qr0 + d);
                float2 b0 = *(const float2*)(Qr0 + d + 32);
                float2 a8 = *(const float2*)(Qr8 + d);
                float2 b8 = *(const float2*)(Qr8 + d + 32);
                float2 c0 = *(const float2*)(cs0 + d);
                float2 s0 = *(const float2*)(sn0 + d);
                float2 c8 = *(const float2*)(cs8 + d);
                float2 s8 = *(const float2*)(sn8 + d);
                // row0
                float lo0x = a0.x * c0.x - b0.x * s0.x;
                float lo0y = a0.y * c0.y - b0.y * s0.y;
                float hi0x = a0.x * s0.x + b0.x * c0.x;
                float hi0y = a0.y * s0.y + b0.y * c0.y;
                // row8
                float lo8x = a8.x * c8.x - b8.x * s8.x;
                float lo8y = a8.y * c8.y - b8.y * s8.y;
                float hi8x = a8.x * s8.x + b8.x * c8.x;
                float hi8y = a8.y * s8.y + b8.y * c8.y;
                qfr[s][0 + 2 * sub]     = packh2(lo0x, lo0y);
                qfr[s][1 + 2 * sub]     = packh2(lo8x, lo8y);
                qfr[s + 2][0 + 2 * sub] = packh2(hi0x, hi0y);
                qfr[s + 2][1 + 2 * sub] = packh2(hi8x, hi8y);
            }
        }
    }

    float o[8][4];
#pragma unroll
    for (int j = 0; j < 8; j++)
#pragma unroll
        for (int r = 0; r < 4; r++) o[j][r] = 0.f;
    float m0 = -1e30f, m1 = -1e30f, l0 = 0.f, l1 = 0.f;

    const int ktmax = 2 * qt + 1;
    for (int kt = 0; kt <= ktmax; kt++) {
        const float* Kbase = Kg + ((size_t)(b * PS + kt * 64)) * (PKV * PHD) + kvh * PHD;
        const float* Vbase = Vg + ((size_t)(b * PS + kt * 64)) * (PKV * PHD) + kvh * PHD;

        __syncthreads();   // previous tile's smem reads complete

        // K tile -> Kh[key][d-pairs]
#pragma unroll
        for (int r = 0; r < 4; r++) {
            int e   = tid + 256 * r;
            int row = e >> 4;
            int ds  = (e & 15) << 2;
            float4 kv = *(const float4*)(Kbase + (size_t)row * (PKV * PHD) + ds);
            uint32_t* kp = Kh + row * ASH + (ds >> 1);
            kp[0] = packh2(kv.x, kv.y);
            kp[1] = packh2(kv.z, kv.w);
        }
        // V tile -> transposed Vt[d][key-pairs]
#pragma unroll
        for (int r = 0; r < 2; r++) {
            int e    = tid + 256 * r;
            int a2   = e >> 4;
            int dcol = (e & 15) << 2;
            const float* r0p = Vbase + (size_t)(2 * a2) * (PKV * PHD) + dcol;
            float4 v0 = *(const float4*)r0p;
            float4 v1 = *(const float4*)(r0p + PKV * PHD);
            Vt[(dcol + 0) * ASH + a2] = packh2(v0.x, v1.x);
            Vt[(dcol + 1) * ASH + a2] = packh2(v0.y, v1.y);
            Vt[(dcol + 2) * ASH + a2] = packh2(v0.z, v1.z);
            Vt[(dcol + 3) * ASH + a2] = packh2(v0.w, v1.w);
        }
        __syncthreads();

        // warp entirely above the diagonal?
        if (kt * 64 > qt * 128 + warp * 16 + 15) continue;

        // S = Q @ K^T : 16 rows x 64 cols in registers
        float s_[8][4];
#pragma unroll
        for (int j = 0; j < 8; j++)
#pragma unroll
            for (int r = 0; r < 4; r++) s_[j][r] = 0.f;

#pragma unroll
        for (int s4 = 0; s4 < 4; s4++) {
#pragma unroll
            for (int j = 0; j < 8; j++) {
                uint32_t bfr[2];
                bfr[0] = Kh[(8 * j + g) * ASH + 8 * s4 + tig];
                bfr[1] = Kh[(8 * j + g) * ASH + 8 * s4 + tig + 4];
                mma_f16(s_[j], qfr[s4], bfr);
            }
        }

        // scale + causal mask
        const bool tail = (kt * 64 + 63 > qr0);
#pragma unroll
        for (int j = 0; j < 8; j++) {
            s_[j][0] *= 0.125f; s_[j][1] *= 0.125f;
            s_[j][2] *= 0.125f; s_[j][3] *= 0.125f;
            if (tail) {
                int kc = kt * 64 + 8 * j + 2 * tig;
                if (kc     > qr0)     s_[j][0] = -1e30f;
                if (kc + 1 > qr0)     s_[j][1] = -1e30f;
                if (kc     > qr0 + 8) s_[j][2] = -1e30f;
                if (kc + 1 > qr0 + 8) s_[j][3] = -1e30f;
            }
        }

        // register online softmax
        float mx0 = -1e30f, mx1 = -1e30f;
#pragma unroll
        for (int j = 0; j < 8; j++) {
            mx0 = fmaxf(mx0, fmaxf(s_[j][0], s_[j][1]));
            mx1 = fmaxf(mx1, fmaxf(s_[j][2], s_[j][3]));
        }
        mx0 = fmaxf(mx0, __shfl_xor_sync(0xffffffffu, mx0, 1));
        mx0 = fmaxf(mx0, __shfl_xor_sync(0xffffffffu, mx0, 2));
        mx1 = fmaxf(mx1, __shfl_xor_sync(0xffffffffu, mx1, 1));
        mx1 = fmaxf(mx1, __shfl_xor_sync(0xffffffffu, mx1, 2));

        float nm0 = fmaxf(m0, mx0), nm1 = fmaxf(m1, mx1);
        float al0 = __expf(m0 - nm0), al1 = __expf(m1 - nm1);
        float sum0 = 0.f, sum1 = 0.f;
        uint32_t pf[4][4];
#pragma unroll
        for (int s4 = 0; s4 < 4; s4++) {
#pragma unroll
            for (int jj = 0; jj < 2; jj++) {
                int j = 2 * s4 + jj;
                float p0 = __expf(s_[j][0] - nm0);
                float p1 = __expf(s_[j][1] - nm0);
                float p2 = __expf(s_[j][2] - nm1);
                float p3 = __expf(s_[j][3] - nm1);
                sum0 += p0 + p1;
                sum1 += p2 + p3;
                pf[s4][2 * jj + 0] = packh2(p0, p1);
                pf[s4][2 * jj + 1] = packh2(p2, p3);
            }
        }
        sum0 += __shfl_xor_sync(0xffffffffu, sum0, 1);
        sum0 += __shfl_xor_sync(0xffffffffu, sum0, 2);
        sum1 += __shfl_xor_sync(0xffffffffu, sum1, 1);
        sum1 += __shfl_xor_sync(0xffffffffu, sum1, 2);

        l0 = l0 * al0 + sum0;
        l1 = l1 * al1 + sum1;
        m0 = nm0; m1 = nm1;

#pragma unroll
        for (int j = 0; j < 8; j++) {
            o[j][0] *= al0; o[j][1] *= al0;
            o[j][2] *= al1; o[j][3] *= al1;
        }

        // O += P @ V
#pragma unroll
        for (int s4 = 0; s4 < 4; s4++) {
#pragma unroll
            for (int j = 0; j < 8; j++) {
                uint32_t bfr[2];
                bfr[0] = Vt[(8 * j + g) * ASH + 8 * s4 + tig];
                bfr[1] = Vt[(8 * j + g) * ASH + 8 * s4 + tig + 4];
                mma_f16(o[j], pf[s4], bfr);
            }
        }
    }

    // epilogue: normalize + store
    float il0 = 1.0f / l0;
    float il1 = 1.0f / l1;
    float* Ob = AO + ((size_t)(b * PS) + qr0) * (PH * PHD) + h * PHD;
#pragma unroll
    for (int j = 0; j < 8; j++) {
        int c0 = 8 * j + 2 * tig;
        *(float2*)(Ob + c0) = make_float2(o[j][0] * il0, o[j][1] * il0);
        *(float2*)(Ob + 8 * (PH * PHD) + c0) = make_float2(o[j][2] * il1, o[j][3] * il1);
    }
}

// ---------------------------------------------------------------------------
// Launch
// ---------------------------------------------------------------------------
extern "C" void kernel_launch(void* const* d_in, const int* in_sizes, int n_in,
                              void* d_out, int out_size)
{
    (void)in_sizes; (void)n_in; (void)out_size;
    const float* x  = (const float*)d_in[0];
    const float* cs = (const float*)d_in[1];
    const float* sn = (const float*)d_in[2];
    const float* Wq = (const float*)d_in[3];
    const float* Wk = (const float*)d_in[4];
    const float* Wv = (const float*)d_in[5];
    const float* Wo = (const float*)d_in[6];
    float* out = (float*)d_out;

    float *Qp, *Kp, *Vp, *AOp;
    cudaGetSymbolAddress((void**)&Qp, g_Q);
    cudaGetSymbolAddress((void**)&Kp, g_K);
    cudaGetSymbolAddress((void**)&Vp, g_V);
    cudaGetSymbolAddress((void**)&AOp, g_AO);

    // Q + K + V projections in one launch (fp16 tensor cores)
    hgemm_qkv<<<dim3(24, PM / 128), 256>>>(x, Wq, Wk, Wv, Qp, Kp, Vp);

    // RoPE on K only (Q rope fused into attention)
    rope_kernel<<<(PM * PKV * 32) / 256, 256>>>(Kp, cs, sn, PKV);

    // causal flash attention (fp16, register softmax, fused Q-rope)
    flash_attn_reg<<<dim3(PS / 128, PH, PB), 256>>>(Qp, Kp, Vp, cs, sn, AOp);

    // output projection (fp16 tensor cores)
    hgemm_one<<<dim3(PD / 128, PM / 128), 256>>>(AOp, Wo, out, PD, PD);
}